// round 2
// baseline (speedup 1.0000x reference)
#include <cuda_runtime.h>

#define B_    64
#define C_    256
#define HW_   1024
#define NPIX  65536
#define NCODE 1024

__device__ float g_a[NPIX];
__device__ float g_c[NCODE];
__device__ int   g_idx[NPIX];

typedef unsigned long long ull;

__device__ __forceinline__ ull fma2(ull a, ull b, ull c) {
    ull d;
    asm("fma.rn.f32x2 %0, %1, %2, %3;" : "=l"(d) : "l"(a), "l"(b), "l"(c));
    return d;
}
__device__ __forceinline__ void unpack2(ull v, float& lo, float& hi) {
    asm("mov.b64 {%0, %1}, %2;" : "=f"(lo), "=f"(hi) : "l"(v));
}

// ---------------------------------------------------------------------------
// c_j = sum_i fl(w[j][i]^2), sequential non-fused adds
// ---------------------------------------------------------------------------
__global__ void c_kernel(const float* __restrict__ w) {
    int j = blockIdx.x * blockDim.x + threadIdx.x;
    if (j < NCODE) {
        const float* r = w + (size_t)j * C_;
        float s = 0.f;
        #pragma unroll 8
        for (int i = 0; i < C_; i++) s = __fadd_rn(s, __fmul_rn(r[i], r[i]));
        g_c[j] = s;
    }
}

// ---------------------------------------------------------------------------
// a_p = sum_i fl(x_p[i]^2), sequential non-fused adds
// ---------------------------------------------------------------------------
__global__ void a_kernel(const float* __restrict__ x) {
    int p = blockIdx.x * blockDim.x + threadIdx.x;
    int b = p >> 10, hw = p & 1023;
    const float* base = x + (size_t)b * C_ * HW_ + hw;
    float s = 0.f;
    #pragma unroll 8
    for (int i = 0; i < C_; i++) {
        float v = base[(size_t)i * HW_];
        s = __fadd_rn(s, __fmul_rn(v, v));
    }
    g_a[p] = s;
}

// ---------------------------------------------------------------------------
// Fused distance GEMM + argmin, packed f32x2 over CODE pairs (FFMA2).
// Block: 64 pixels x 1024 codes (4 chunks of 256 codes, 4 k-chunks of 64).
// smem:
//   xsd : ull[256][64]   duplicated (x,x) per pixel, 128 KB
//   ws  : float[64][260] w tile, column-swizzled:  stored col = c ^ sw(k),
//         sw(k) = ((k>>1)&7)<<2  -> conflict-free k-major stores AND
//         4-consecutive-code LDS.128 reads (xor is a multiple of 4).
// Thread (tx=t&15, ty=t>>4): pixels {2ty,2ty+1,2ty+32,2ty+33},
//                            codes  {4tx+64u+j : u<4, j<4}.
// Accumulation order over k is identical to the scalar version ->
// dot products are bitwise identical -> argmin identical.
// ---------------------------------------------------------------------------
#define WS_STRIDE 260
#define SM_ULL    (256 * 64)            // xsd size in ull
__global__ void __launch_bounds__(256, 1)
argmin_kernel(const float* __restrict__ x, const float* __restrict__ wt,
              float* __restrict__ out_idx, int write_idx) {
    extern __shared__ ull sm_u[];
    ull*   xsd = sm_u;                               // [256][64]
    float* wsf = (float*)(sm_u + SM_ULL);            // [64][260]
    float* smf = (float*)sm_u;                       // reuse for reduction

    int t    = threadIdx.x;
    int tx   = t & 15, ty = t >> 4;
    int lane16 = t & 15;

    int pix_base = blockIdx.x * 64;                  // 16 blocks per image
    int b  = pix_base >> 10;
    int hw = pix_base & 1023;
    const float* xb = x + (size_t)b * C_ * HW_ + hw;

    // ---- load x tile, duplicated (v,v) per pixel, STS.128 conflict-free ----
    #pragma unroll 4
    for (int it = 0; it < 16; it++) {
        int k = (t >> 4) + 16 * it;
        float4 v = *reinterpret_cast<const float4*>(xb + (size_t)k * HW_ + 4 * lane16);
        float4 d0 = make_float4(v.x, v.x, v.y, v.y);
        float4 d1 = make_float4(v.z, v.z, v.w, v.w);
        float4* dst = reinterpret_cast<float4*>(xsd + (size_t)k * 64 + 4 * lane16);
        dst[0] = d0;
        dst[1] = d1;
    }

    float a_reg[4], bd[4];
    int   bi[4];
    #pragma unroll
    for (int px = 0; px < 4; px++) {
        int p = 2 * ty + 32 * (px >> 1) + (px & 1);
        a_reg[px] = g_a[pix_base + p];
        bd[px]    = 3.4e38f;
        bi[px]    = 0;
    }

    for (int cc = 0; cc < 4; cc++) {
        ull acc[4][8];
        #pragma unroll
        for (int px = 0; px < 4; px++)
            #pragma unroll
            for (int cq = 0; cq < 8; cq++) acc[px][cq] = 0ull;

        for (int kc = 0; kc < 4; kc++) {
            __syncthreads();
            // ---- load w tile: 64 k x 256 codes, swizzled columns ----
            #pragma unroll
            for (int it = 0; it < 16; it++) {
                int f    = t + 256 * it;
                int code = f >> 4;
                int kq   = f & 15;
                float4 v = *reinterpret_cast<const float4*>(
                    wt + (size_t)(cc * 256 + code) * C_ + kc * 64 + 4 * kq);
                int k0 = 4 * kq;
                wsf[(k0 + 0) * WS_STRIDE + (code ^ ((((k0 + 0) >> 1) & 7) << 2))] = v.x;
                wsf[(k0 + 1) * WS_STRIDE + (code ^ ((((k0 + 1) >> 1) & 7) << 2))] = v.y;
                wsf[(k0 + 2) * WS_STRIDE + (code ^ ((((k0 + 2) >> 1) & 7) << 2))] = v.z;
                wsf[(k0 + 3) * WS_STRIDE + (code ^ ((((k0 + 3) >> 1) & 7) << 2))] = v.w;
            }
            __syncthreads();

            #pragma unroll 2
            for (int kk = 0; kk < 64; kk++) {
                int k = kc * 64 + kk;
                const ull* xrow = xsd + (size_t)k * 64;
                ulonglong2 xa  = *reinterpret_cast<const ulonglong2*>(xrow + 2 * ty);
                ulonglong2 xb2 = *reinterpret_cast<const ulonglong2*>(xrow + 2 * ty + 32);
                int sw = ((kk >> 1) & 7) << 2;
                const float* wrow = wsf + kk * WS_STRIDE;
                ulonglong2 wq[4];
                #pragma unroll
                for (int u = 0; u < 4; u++)
                    wq[u] = *reinterpret_cast<const ulonglong2*>(
                        wrow + ((4 * tx + 64 * u) ^ sw));
                #pragma unroll
                for (int u = 0; u < 4; u++) {
                    ull wlo = wq[u].x, whi = wq[u].y;
                    acc[0][2*u+0] = fma2(xa.x,  wlo, acc[0][2*u+0]);
                    acc[1][2*u+0] = fma2(xa.y,  wlo, acc[1][2*u+0]);
                    acc[2][2*u+0] = fma2(xb2.x, wlo, acc[2][2*u+0]);
                    acc[3][2*u+0] = fma2(xb2.y, wlo, acc[3][2*u+0]);
                    acc[0][2*u+1] = fma2(xa.x,  whi, acc[0][2*u+1]);
                    acc[1][2*u+1] = fma2(xa.y,  whi, acc[1][2*u+1]);
                    acc[2][2*u+1] = fma2(xb2.x, whi, acc[2][2*u+1]);
                    acc[3][2*u+1] = fma2(xb2.y, whi, acc[3][2*u+1]);
                }
            }
        }

        // ---- chunk epilogue, ascending j -> first-index-on-tie preserved ----
        #pragma unroll
        for (int u = 0; u < 4; u++)
            #pragma unroll
            for (int h = 0; h < 2; h++) {
                int j0 = cc * 256 + 4 * tx + 64 * u + 2 * h;
                float c0 = g_c[j0], c1 = g_c[j0 + 1];
                #pragma unroll
                for (int px = 0; px < 4; px++) {
                    float dlo, dhi;
                    unpack2(acc[px][2*u+h], dlo, dhi);
                    float d2a = __fadd_rn(fmaf(-2.f, dlo, a_reg[px]), c0);
                    if (d2a < bd[px] || (d2a == bd[px] && j0 < bi[px])) {
                        bd[px] = d2a; bi[px] = j0;
                    }
                    float d2b = __fadd_rn(fmaf(-2.f, dhi, a_reg[px]), c1);
                    if (d2b < bd[px] || (d2b == bd[px] && (j0+1) < bi[px])) {
                        bd[px] = d2b; bi[px] = j0 + 1;
                    }
                }
            }
    }

    // ---- cross-tx reduction: 16 candidates per pixel ----
    __syncthreads();
    float* rd = smf;                       // [64][16]
    int*   ri = (int*)(smf + 1024);        // [64][16]
    #pragma unroll
    for (int px = 0; px < 4; px++) {
        int p = 2 * ty + 32 * (px >> 1) + (px & 1);
        rd[p * 16 + tx] = bd[px];
        ri[p * 16 + tx] = bi[px];
    }
    __syncthreads();
    if (t < 64) {
        float best = rd[t * 16];
        int   bj   = ri[t * 16];
        #pragma unroll
        for (int s = 1; s < 16; s++) {
            float d = rd[t * 16 + s];
            int   j = ri[t * 16 + s];
            if (d < best || (d == best && j < bj)) { best = d; bj = j; }
        }
        g_idx[pix_base + t] = bj;
        if (write_idx) out_idx[pix_base + t] = (float)bj;
    }
}

// ---------------------------------------------------------------------------
// Scatter: quantized[b][ci][hw] = w[idx][ci]; ste = fl(fl(q-x)+x).
// Two channel passes of 128 -> 66 KB smem -> 3 blocks/SM.
// ---------------------------------------------------------------------------
__global__ void __launch_bounds__(256, 3)
scatter_kernel(const float* __restrict__ x, const float* __restrict__ wt,
               float* __restrict__ out_q, float* __restrict__ out_ste,
               int has_ste) {
    extern __shared__ float sm[];          // [128][129]
    __shared__ int lidx[128];

    int t = threadIdx.x, lane = t & 31, warp = t >> 5;
    int pix_base = blockIdx.x * 128;
    int b  = pix_base >> 10;
    int hw = pix_base & 1023;

    if (t < 128) lidx[t] = g_idx[pix_base + t];

    for (int pass = 0; pass < 2; pass++) {
        __syncthreads();
        // gather 128 rows x 128 channels (coalesced reads, transposed stores)
        for (int rit = 0; rit < 16; rit++) {
            int r = warp + 8 * rit;
            const float* row = wt + (size_t)lidx[r] * C_ + pass * 128;
            #pragma unroll
            for (int kit = 0; kit < 4; kit++) {
                int cl = lane + 32 * kit;
                sm[cl * 129 + r] = row[cl];
            }
        }
        __syncthreads();

        int hw_l = t & 127;
        int ch   = t >> 7;                 // 0..1
        for (int cit = 0; cit < 64; cit++) {
            int cl = ch + 2 * cit;
            int ci = pass * 128 + cl;
            size_t o = (size_t)b * C_ * HW_ + (size_t)ci * HW_ + hw + hw_l;
            float q = sm[cl * 129 + hw_l];
            out_q[o] = q;
            if (has_ste) {
                float xv = x[o];
                out_ste[o] = __fadd_rn(__fsub_rn(q, xv), xv);
            }
        }
    }
}

// ---------------------------------------------------------------------------
extern "C" void kernel_launch(void* const* d_in, const int* in_sizes, int n_in,
                              void* d_out, int out_size) {
    const float* x  = (const float*)d_in[0];
    const float* wt = (const float*)d_in[1];
    float* out = (float*)d_out;

    const long long qsz = (long long)NPIX * C_;  // 16777216
    int has_ste = (out_size >= (int)(2 * qsz)) ? 1 : 0;
    int has_idx = (out_size >= (int)(2 * qsz) + NPIX) ||
                  (out_size == (int)qsz + NPIX);
    float* out_q   = out;
    float* out_ste = out + qsz;
    float* out_idx = has_ste ? out + 2 * qsz : out + qsz;

    const int argmin_smem = SM_ULL * 8 + 64 * WS_STRIDE * 4;   // 197632
    cudaFuncSetAttribute(argmin_kernel,
        cudaFuncAttributeMaxDynamicSharedMemorySize, argmin_smem);
    cudaFuncSetAttribute(scatter_kernel,
        cudaFuncAttributeMaxDynamicSharedMemorySize, 66048);

    c_kernel<<<4, 256>>>(wt);
    a_kernel<<<NPIX / 256, 256>>>(x);
    argmin_kernel<<<NPIX / 64, 256, argmin_smem>>>(x, wt, out_idx, has_idx ? 1 : 0);
    scatter_kernel<<<NPIX / 128, 256, 66048>>>(x, wt, out_q, out_ste, has_ste);
}

// round 3
// speedup vs baseline: 3.1088x; 3.1088x over previous
#include <cuda_runtime.h>
#include <cuda_bf16.h>
#include <cuda_fp16.h>

#define B_    64
#define C_    256
#define HW_   1024
#define NPIX  65536
#define NCODE 1024
#define CAP   16
#define MARGIN 1e-3f

__device__ float g_a[NPIX];
__device__ float g_c[NCODE];
__device__ int   g_idx[NPIX];
__device__ float g_xT[(size_t)NPIX * C_];             // 64MB  fp32 x, pixel-major
__device__ unsigned short g_xbf[(size_t)NPIX * C_];   // 32MB  bf16 x, pixel-major
__device__ unsigned short g_wbf[NCODE * C_];          // 512KB bf16 codebook
__device__ unsigned short g_h[(size_t)NPIX * NCODE];  // 128MB fp16 (c - 2dot)
__device__ short g_cand[NPIX * CAP];
__device__ int   g_ccnt[NPIX];

// monotone float<->uint key for atomicMin on signed floats
__device__ __forceinline__ unsigned fkey(float f) {
    unsigned u = __float_as_uint(f);
    return (u & 0x80000000u) ? ~u : (u | 0x80000000u);
}
__device__ __forceinline__ float unfkey(unsigned k) {
    unsigned u = (k & 0x80000000u) ? (k & 0x7fffffffu) : ~k;
    return __uint_as_float(u);
}

__device__ __forceinline__ void ldm4(unsigned* r, unsigned addr) {
    asm volatile("ldmatrix.sync.aligned.m8n8.x4.shared.b16 {%0,%1,%2,%3}, [%4];"
                 : "=r"(r[0]), "=r"(r[1]), "=r"(r[2]), "=r"(r[3]) : "r"(addr));
}
__device__ __forceinline__ void mma16816(float* d, const unsigned* a,
                                         unsigned b0, unsigned b1) {
    asm volatile(
        "mma.sync.aligned.m16n8k16.row.col.f32.bf16.bf16.f32 "
        "{%0,%1,%2,%3}, {%4,%5,%6,%7}, {%8,%9}, {%0,%1,%2,%3};"
        : "+f"(d[0]), "+f"(d[1]), "+f"(d[2]), "+f"(d[3])
        : "r"(a[0]), "r"(a[1]), "r"(a[2]), "r"(a[3]), "r"(b0), "r"(b1));
}

// ---------------------------------------------------------------------------
// c_j = sum fl(w^2) sequential (exact, matches round-1)
// ---------------------------------------------------------------------------
__global__ void c_kernel(const float* __restrict__ w) {
    int j = blockIdx.x * blockDim.x + threadIdx.x;
    if (j < NCODE) {
        const float* r = w + (size_t)j * C_;
        float s = 0.f;
        #pragma unroll 8
        for (int i = 0; i < C_; i++) s = __fadd_rn(s, __fmul_rn(r[i], r[i]));
        g_c[j] = s;
    }
}

// ---------------------------------------------------------------------------
// codebook -> bf16
// ---------------------------------------------------------------------------
__global__ void wcvt_kernel(const float* __restrict__ w) {
    int i = blockIdx.x * blockDim.x + threadIdx.x;   // over pairs
    if (i < NCODE * C_ / 2) {
        float2 v = reinterpret_cast<const float2*>(w)[i];
        __nv_bfloat162 b2 = __floats2bfloat162_rn(v.x, v.y);
        reinterpret_cast<unsigned*>(g_wbf)[i] = *reinterpret_cast<unsigned*>(&b2);
    }
}

// ---------------------------------------------------------------------------
// Transpose x (B,C,H,W)->(pix,k) fp32 + bf16, and a_p = sum fl(x^2) seq.
// Block: 128 pixels x 256 channels. smem tile [256][132].
// ---------------------------------------------------------------------------
__global__ void __launch_bounds__(256, 1)
t_kernel(const float* __restrict__ x) {
    extern __shared__ float sm[];                    // [256][132]
    int t = threadIdx.x;
    int pixbase = blockIdx.x * 128;
    int b  = pixbase >> 10;
    int hw0 = pixbase & 1023;
    const float* xb = x + (size_t)b * C_ * HW_ + hw0;

    #pragma unroll 8
    for (int it = 0; it < 32; it++) {
        int idx = t + 256 * it;
        int c = idx >> 5, hq = idx & 31;
        float4 v = *reinterpret_cast<const float4*>(xb + (size_t)c * HW_ + 4 * hq);
        *reinterpret_cast<float4*>(&sm[c * 132 + 4 * hq]) = v;
    }
    __syncthreads();

    if (t < 128) {
        float s = 0.f;
        for (int k = 0; k < C_; k++) {
            float v = sm[k * 132 + t];
            s = __fadd_rn(s, __fmul_rn(v, v));
        }
        g_a[pixbase + t] = s;
    }

    #pragma unroll 4
    for (int it = 0; it < 32; it++) {
        int idx = t + 256 * it;
        int pl = idx >> 6, kq = idx & 63;
        float v0 = sm[(4 * kq + 0) * 132 + pl];
        float v1 = sm[(4 * kq + 1) * 132 + pl];
        float v2 = sm[(4 * kq + 2) * 132 + pl];
        float v3 = sm[(4 * kq + 3) * 132 + pl];
        size_t o = (size_t)(pixbase + pl) * C_ + 4 * kq;
        *reinterpret_cast<float4*>(g_xT + o) = make_float4(v0, v1, v2, v3);
        __nv_bfloat162 b01 = __floats2bfloat162_rn(v0, v1);
        __nv_bfloat162 b23 = __floats2bfloat162_rn(v2, v3);
        uint2 u = make_uint2(*reinterpret_cast<unsigned*>(&b01),
                             *reinterpret_cast<unsigned*>(&b23));
        *reinterpret_cast<uint2*>(g_xbf + o) = u;
    }
}

// ---------------------------------------------------------------------------
// bf16 MMA screen: h[pix][code] = c_j - 2*dot (fp16), per-pixel min,
// candidate lists within MARGIN.
// Block: 128 pix x 1024 codes (16 chunks of 64). 8 warps: wm=wid>>1, wn=wid&1.
// ---------------------------------------------------------------------------
__global__ void __launch_bounds__(256, 2)
g_kernel() {
    extern __shared__ unsigned short smem_g[];
    unsigned short* xs = smem_g;               // [128][256] swizzled, 64KB
    unsigned short* ws = smem_g + 128 * 256;   // [64][256]  swizzled, 32KB
    __shared__ float    cs[NCODE];
    __shared__ unsigned minkey[128];
    __shared__ int      cnt_s[128];
    __shared__ short    cand_s[128 * CAP];

    int t = threadIdx.x, lane = t & 31, wid = t >> 5;
    int wm = wid >> 1, wn = wid & 1;
    int pixbase = blockIdx.x * 128;

    for (int i = t; i < NCODE; i += 256) cs[i] = g_c[i];
    if (t < 128) { minkey[t] = 0xFFFFFFFFu; cnt_s[t] = 0; }

    // load x tile (16B granules, XOR-swizzled by row&7)
    #pragma unroll 4
    for (int it = 0; it < 16; it++) {
        int flat = t + 256 * it;
        int pl = flat >> 5, gq = flat & 31;
        uint4 v = reinterpret_cast<const uint4*>(
            g_xbf + (size_t)(pixbase + pl) * C_)[gq];
        *reinterpret_cast<uint4*>(
            reinterpret_cast<char*>(xs) + pl * 512 + ((gq ^ (pl & 7)) * 16)) = v;
    }

    unsigned xs_u = (unsigned)__cvta_generic_to_shared(xs);
    unsigned ws_u = (unsigned)__cvta_generic_to_shared(ws);

    // ldmatrix lane address pieces
    int asub = lane >> 3;
    int arow = (asub & 1) * 8 + (lane & 7);
    int acg  = asub >> 1;
    unsigned a_base[2];
    #pragma unroll
    for (int mt = 0; mt < 2; mt++)
        a_base[mt] = xs_u + (wm * 32 + mt * 16 + arow) * 512;
    int arx = arow & 7;

    int bcode = (lane & 7) + ((lane >> 4) & 1) * 8;
    int bkg   = (lane >> 3) & 1;
    unsigned b_base[2];
    #pragma unroll
    for (int n2 = 0; n2 < 2; n2++)
        b_base[n2] = ws_u + (wn * 32 + n2 * 16 + bcode) * 512;
    int brx = bcode & 7;

    float fmn[4] = {3.4e38f, 3.4e38f, 3.4e38f, 3.4e38f};

    for (int cc = 0; cc < 16; cc++) {
        __syncthreads();
        #pragma unroll
        for (int it = 0; it < 8; it++) {
            int flat = t + 256 * it;
            int cl = flat >> 5, gq = flat & 31;
            uint4 v = reinterpret_cast<const uint4*>(
                g_wbf + (size_t)(cc * 64 + cl) * C_)[gq];
            *reinterpret_cast<uint4*>(
                reinterpret_cast<char*>(ws) + cl * 512 + ((gq ^ (cl & 7)) * 16)) = v;
        }
        __syncthreads();

        float d[2][4][4];
        #pragma unroll
        for (int mt = 0; mt < 2; mt++)
            #pragma unroll
            for (int nt = 0; nt < 4; nt++)
                #pragma unroll
                for (int r = 0; r < 4; r++) d[mt][nt][r] = 0.f;

        #pragma unroll 4
        for (int ks = 0; ks < 16; ks++) {
            unsigned a[2][4], bf[2][4];
            #pragma unroll
            for (int mt = 0; mt < 2; mt++) {
                unsigned g = (unsigned)((2 * ks + acg) ^ arx);
                ldm4(a[mt], a_base[mt] + g * 16);
            }
            #pragma unroll
            for (int n2 = 0; n2 < 2; n2++) {
                unsigned g = (unsigned)((2 * ks + bkg) ^ brx);
                ldm4(bf[n2], b_base[n2] + g * 16);
            }
            #pragma unroll
            for (int mt = 0; mt < 2; mt++)
                #pragma unroll
                for (int nt = 0; nt < 4; nt++)
                    mma16816(d[mt][nt], a[mt],
                             bf[nt >> 1][(nt & 1) * 2], bf[nt >> 1][(nt & 1) * 2 + 1]);
        }

        // epilogue: h = fmaf(-2,dot,c), fp16 store, min track
        #pragma unroll
        for (int mt = 0; mt < 2; mt++)
            #pragma unroll
            for (int half = 0; half < 2; half++) {
                int row = wm * 32 + mt * 16 + (lane >> 2) + half * 8;
                size_t hrow = (size_t)(pixbase + row) * NCODE;
                float mloc = fmn[mt * 2 + half];
                #pragma unroll
                for (int nt = 0; nt < 4; nt++) {
                    int j0 = cc * 64 + wn * 32 + nt * 8 + 2 * (lane & 3);
                    float f0 = fmaf(-2.f, d[mt][nt][half * 2 + 0], cs[j0]);
                    float f1 = fmaf(-2.f, d[mt][nt][half * 2 + 1], cs[j0 + 1]);
                    mloc = fminf(mloc, fminf(f0, f1));
                    unsigned hp =
                        ((unsigned)__half_as_ushort(__float2half_rn(f1)) << 16) |
                        (unsigned)__half_as_ushort(__float2half_rn(f0));
                    *reinterpret_cast<unsigned*>(g_h + hrow + j0) = hp;
                }
                fmn[mt * 2 + half] = mloc;
            }
    }

    #pragma unroll
    for (int s = 0; s < 4; s++) {
        int row = wm * 32 + (s >> 1) * 16 + (lane >> 2) + (s & 1) * 8;
        atomicMin(&minkey[row], fkey(fmn[s]));
    }
    __syncthreads();   // also makes this block's g_h stores visible block-wide

    // screening: warp wid handles pixels wid + 8*i
    for (int i = 0; i < 16; i++) {
        int p = wid + 8 * i;
        float thr = unfkey(minkey[p]) + MARGIN;
        const unsigned* hrow = reinterpret_cast<const unsigned*>(
            g_h + (size_t)(pixbase + p) * NCODE);
        for (int it = 0; it < 16; it++) {
            int idx = lane + 32 * it;
            unsigned v = hrow[idx];
            float f0 = __half2float(__ushort_as_half((unsigned short)(v & 0xffff)));
            float f1 = __half2float(__ushort_as_half((unsigned short)(v >> 16)));
            if (f0 <= thr) {
                int sl = atomicAdd(&cnt_s[p], 1);
                if (sl < CAP) cand_s[p * CAP + sl] = (short)(2 * idx);
            }
            if (f1 <= thr) {
                int sl = atomicAdd(&cnt_s[p], 1);
                if (sl < CAP) cand_s[p * CAP + sl] = (short)(2 * idx + 1);
            }
        }
    }
    __syncthreads();
    if (t < 128) {
        g_ccnt[pixbase + t] = cnt_s[t];
        int4* dst = reinterpret_cast<int4*>(g_cand) + (size_t)(pixbase + t) * 2;
        const int4* src = reinterpret_cast<const int4*>(cand_s) + t * 2;
        dst[0] = src[0];
        dst[1] = src[1];
    }
}

// ---------------------------------------------------------------------------
// Exact rescreen: per candidate, sequential-k fp32 fmaf dot (round-1 verbatim),
// lexicographic (d2, j) argmin. 32 pixels x 8 slots per block.
// ---------------------------------------------------------------------------
__global__ void __launch_bounds__(256, 4)
s2_kernel(const float* __restrict__ wt, float* __restrict__ out_idx,
          int write_idx) {
    __shared__ float sd[256];
    __shared__ int   sj[256];
    int t = threadIdx.x;
    int pix = blockIdx.x * 32 + (t >> 3);
    int sl = t & 7;

    int cnt = g_ccnt[pix];
    const float4* xr = reinterpret_cast<const float4*>(g_xT + (size_t)pix * C_);
    float a = g_a[pix];
    float bd = 3.4e38f;
    int   bj = 1 << 30;

    if (cnt <= CAP) {
        for (int s = sl; s < cnt; s += 8) {
            int j = g_cand[pix * CAP + s];
            const float4* wr = reinterpret_cast<const float4*>(wt + (size_t)j * C_);
            float dot = 0.f;
            #pragma unroll 8
            for (int q = 0; q < 64; q++) {
                float4 xv = xr[q], wv = wr[q];
                dot = fmaf(xv.x, wv.x, dot);
                dot = fmaf(xv.y, wv.y, dot);
                dot = fmaf(xv.z, wv.z, dot);
                dot = fmaf(xv.w, wv.w, dot);
            }
            float d2 = __fadd_rn(fmaf(-2.f, dot, a), g_c[j]);
            if (d2 < bd || (d2 == bd && j < bj)) { bd = d2; bj = j; }
        }
    } else {  // overflow fallback: exact full scan
        for (int j = sl; j < NCODE; j += 8) {
            const float4* wr = reinterpret_cast<const float4*>(wt + (size_t)j * C_);
            float dot = 0.f;
            #pragma unroll 8
            for (int q = 0; q < 64; q++) {
                float4 xv = xr[q], wv = wr[q];
                dot = fmaf(xv.x, wv.x, dot);
                dot = fmaf(xv.y, wv.y, dot);
                dot = fmaf(xv.z, wv.z, dot);
                dot = fmaf(xv.w, wv.w, dot);
            }
            float d2 = __fadd_rn(fmaf(-2.f, dot, a), g_c[j]);
            if (d2 < bd || (d2 == bd && j < bj)) { bd = d2; bj = j; }
        }
    }
    sd[t] = bd; sj[t] = bj;
    __syncthreads();
    if (sl == 0) {
        #pragma unroll
        for (int k = 1; k < 8; k++) {
            float d = sd[t + k]; int j = sj[t + k];
            if (d < bd || (d == bd && j < bj)) { bd = d; bj = j; }
        }
        g_idx[pix] = bj;
        if (write_idx) out_idx[pix] = (float)bj;
    }
}

// ---------------------------------------------------------------------------
// Scatter (round-1 version, verbatim): q = w[idx], ste = fl(fl(q-x)+x)
// ---------------------------------------------------------------------------
__global__ void __launch_bounds__(256, 1)
scatter_kernel(const float* __restrict__ x, const float* __restrict__ wt,
               float* __restrict__ out_q, float* __restrict__ out_ste,
               int has_ste) {
    extern __shared__ float sm[];          // [256][129]
    __shared__ int lidx[128];

    int t = threadIdx.x, lane = t & 31, warp = t >> 5;
    int pix_base = blockIdx.x * 128;
    int b  = pix_base >> 10;
    int hw = pix_base & 1023;

    if (t < 128) lidx[t] = g_idx[pix_base + t];
    __syncthreads();

    for (int rit = 0; rit < 16; rit++) {
        int r = warp + 8 * rit;
        const float* row = wt + (size_t)lidx[r] * C_;
        #pragma unroll
        for (int kit = 0; kit < 8; kit++) {
            int ci = lane + 32 * kit;
            sm[ci * 129 + r] = row[ci];
        }
    }
    __syncthreads();

    int hw_l = t & 127;
    int ch   = t >> 7;
    for (int cit = 0; cit < 128; cit++) {
        int ci = ch + 2 * cit;
        size_t o = (size_t)b * C_ * HW_ + (size_t)ci * HW_ + hw + hw_l;
        float q = sm[ci * 129 + hw_l];
        out_q[o] = q;
        if (has_ste) {
            float xv = x[o];
            out_ste[o] = __fadd_rn(__fsub_rn(q, xv), xv);
        }
    }
}

// ---------------------------------------------------------------------------
extern "C" void kernel_launch(void* const* d_in, const int* in_sizes, int n_in,
                              void* d_out, int out_size) {
    const float* x  = (const float*)d_in[0];
    const float* wt = (const float*)d_in[1];
    float* out = (float*)d_out;

    const long long qsz = (long long)NPIX * C_;
    int has_ste = (out_size >= (int)(2 * qsz)) ? 1 : 0;
    int has_idx = (out_size >= (int)(2 * qsz) + NPIX) ||
                  (out_size == (int)qsz + NPIX);
    float* out_q   = out;
    float* out_ste = out + qsz;
    float* out_idx = has_ste ? out + 2 * qsz : out + qsz;

    cudaFuncSetAttribute(t_kernel,
        cudaFuncAttributeMaxDynamicSharedMemorySize, 256 * 132 * 4);
    cudaFuncSetAttribute(g_kernel,
        cudaFuncAttributeMaxDynamicSharedMemorySize, 98304);
    cudaFuncSetAttribute(scatter_kernel,
        cudaFuncAttributeMaxDynamicSharedMemorySize, 132096);

    c_kernel<<<4, 256>>>(wt);
    wcvt_kernel<<<NCODE * C_ / 2 / 256, 256>>>(wt);
    t_kernel<<<NPIX / 128, 256, 256 * 132 * 4>>>(x);
    g_kernel<<<NPIX / 128, 256, 98304>>>();
    s2_kernel<<<NPIX / 32, 256>>>(wt, out_idx, has_idx ? 1 : 0);
    scatter_kernel<<<NPIX / 128, 256, 132096>>>(x, wt, out_q, out_ste, has_ste);
}